// round 6
// baseline (speedup 1.0000x reference)
#include <cuda_runtime.h>
#include <cuda_bf16.h>
#include <cstdint>
#include <math.h>

// Problem constants: B=32, S=64, E=256, H=4, D=64
#define NROWS 2048
#define EDIM  256
#define NQKV  768
#define NH    4

#define LDT 72   // padded smem row stride (bf16 elems)

// ---------------- scratch (__device__ globals, no allocs) -------------------
__device__ __nv_bfloat16 g_EOhi[NROWS * EDIM], g_EOlo[NROWS * EDIM]; // exp(attn out)
__device__ float g_Y[NROWS * NQKV];  // q,k: sum*exp(bias); v: log(sum)+bv

// ---------------- helpers (base ISA only — sm_103 non-variant) --------------
__device__ __forceinline__ uint32_t smem_u32(const void* p) {
    uint32_t a;
    asm("{ .reg .u64 t; cvta.to.shared.u64 t, %1; cvt.u32.u64 %0, t; }"
        : "=r"(a) : "l"(p));
    return a;
}
__device__ __forceinline__ void ldsm_x4(uint32_t* r, uint32_t addr) {
    asm volatile("ldmatrix.sync.aligned.m8n8.x4.shared.b16 {%0,%1,%2,%3}, [%4];"
                 : "=r"(r[0]), "=r"(r[1]), "=r"(r[2]), "=r"(r[3]) : "r"(addr));
}
__device__ __forceinline__ void mma16816(float* d, const uint32_t* a,
                                         uint32_t b0, uint32_t b1) {
    asm volatile(
        "mma.sync.aligned.m16n8k16.row.col.f32.bf16.bf16.f32 "
        "{%0,%1,%2,%3}, {%4,%5,%6,%7}, {%8,%9}, {%0,%1,%2,%3};"
        : "+f"(d[0]), "+f"(d[1]), "+f"(d[2]), "+f"(d[3])
        : "r"(a[0]), "r"(a[1]), "r"(a[2]), "r"(a[3]), "r"(b0), "r"(b1));
}
// exp + hi/lo split of a float4 -> two packed uint2 (4 bf16 each)
__device__ __forceinline__ void exp_split4(const float4& v, uint2& hi, uint2& lo) {
    float e[4] = {__expf(v.x), __expf(v.y), __expf(v.z), __expf(v.w)};
    __nv_bfloat16 h[4], l[4];
    #pragma unroll
    for (int j = 0; j < 4; ++j) {
        h[j] = __float2bfloat16(e[j]);
        l[j] = __float2bfloat16(e[j] - __bfloat162float(h[j]));
    }
    __nv_bfloat162 h0 = __halves2bfloat162(h[0], h[1]);
    __nv_bfloat162 h1 = __halves2bfloat162(h[2], h[3]);
    __nv_bfloat162 l0 = __halves2bfloat162(l[0], l[1]);
    __nv_bfloat162 l1 = __halves2bfloat162(l[2], l[3]);
    hi.x = *(uint32_t*)&h0; hi.y = *(uint32_t*)&h1;
    lo.x = *(uint32_t*)&l0; lo.y = *(uint32_t*)&l1;
}

// ---------------------------------------------------------------------------
// Fused exp + bf16x3 GEMM via mma.sync.
//   C[m,n] = sum_k exp?(A)[m,k] * exp(B)[n,k], fp32 accumulate.
//   CTA 64x64, 256 threads (8 warps, 2m x 4n, warp tile 32x16), K=256 in 4x64.
//   MODE 0: A = x fp32 (exp in-kernel), B = Wq/Wk/Wv fp32 (exp in-kernel)
//           epilogue: n<256 -> acc*exp(bq), n<512 -> acc*exp(bk), else log+bv
//   MODE 1: A = EO bf16 hi/lo (precomputed), B = Wo fp32 (exp in-kernel)
//           epilogue: log(acc)+bo
// ---------------------------------------------------------------------------
template<int MODE>
__global__ void __launch_bounds__(256) k_tg(
    const void* __restrict__ Ap, const void* __restrict__ Alp,
    const float* __restrict__ W0, const float* __restrict__ W1,
    const float* __restrict__ W2,
    float* __restrict__ C, int ldc,
    const float* __restrict__ b0, const float* __restrict__ b1,
    const float* __restrict__ b2)
{
    __shared__ __align__(16) __nv_bfloat16 sAhi[64 * LDT];
    __shared__ __align__(16) __nv_bfloat16 sAlo[64 * LDT];
    __shared__ __align__(16) __nv_bfloat16 sBhi[64 * LDT];
    __shared__ __align__(16) __nv_bfloat16 sBlo[64 * LDT];

    const int tid  = threadIdx.x;
    const int lane = tid & 31;
    const int warp = tid >> 5;
    const int wm   = (warp & 1) * 32;     // warp row offset
    const int wn   = (warp >> 1) * 16;    // warp col offset
    const int m0 = blockIdx.y * 64;
    const int n0 = blockIdx.x * 64;

    // B source (row-major [n][k] fp32; exp applied here)
    const int region = (MODE == 0) ? (n0 >> 8) : 0;
    const float* Wsrc = (MODE == 0)
        ? (region == 0 ? W0 : (region == 1 ? W1 : W2)) : W0;
    const int bRow0 = (MODE == 0) ? (n0 & 255) : n0;

    // per-thread load coords
    // fp32 path: 1024 float4-chunks per 64x64 tile, 4/thread: r=c>>4, k4=(c&15)*4
    // bf16 path (MODE1 A): 512 uint4-chunks, 2/thread: r=c>>3, k8=(c&7)*8

    // prefetch registers
    float4 ra[4], rb[4];
    uint4  rahi[2], ralo[2];
    // converted bf16 registers
    uint2 cah[4], cal[4], cbh[4], cbl[4];

    auto loadRegs = [&](int kc) {
        const int kb = kc * 64;
        #pragma unroll
        for (int i = 0; i < 4; ++i) {
            int c = tid + 256 * i;
            int r = c >> 4, k4 = (c & 15) * 4;
            rb[i] = *(const float4*)&Wsrc[(bRow0 + r) * EDIM + kb + k4];
        }
        if (MODE == 0) {
            #pragma unroll
            for (int i = 0; i < 4; ++i) {
                int c = tid + 256 * i;
                int r = c >> 4, k4 = (c & 15) * 4;
                ra[i] = *(const float4*)&((const float*)Ap)[(m0 + r) * EDIM + kb + k4];
            }
        } else {
            #pragma unroll
            for (int i = 0; i < 2; ++i) {
                int c = tid + 256 * i;
                int r = c >> 3, k8 = (c & 7) * 8;
                rahi[i] = *(const uint4*)&((const __nv_bfloat16*)Ap)[(m0 + r) * EDIM + kb + k8];
                ralo[i] = *(const uint4*)&((const __nv_bfloat16*)Alp)[(m0 + r) * EDIM + kb + k8];
            }
        }
    };
    auto convRegs = [&]() {
        #pragma unroll
        for (int i = 0; i < 4; ++i) exp_split4(rb[i], cbh[i], cbl[i]);
        if (MODE == 0) {
            #pragma unroll
            for (int i = 0; i < 4; ++i) exp_split4(ra[i], cah[i], cal[i]);
        }
    };
    auto storeSmem = [&]() {
        #pragma unroll
        for (int i = 0; i < 4; ++i) {
            int c = tid + 256 * i;
            int r = c >> 4, k4 = (c & 15) * 4;
            *(uint2*)&sBhi[r * LDT + k4] = cbh[i];
            *(uint2*)&sBlo[r * LDT + k4] = cbl[i];
        }
        if (MODE == 0) {
            #pragma unroll
            for (int i = 0; i < 4; ++i) {
                int c = tid + 256 * i;
                int r = c >> 4, k4 = (c & 15) * 4;
                *(uint2*)&sAhi[r * LDT + k4] = cah[i];
                *(uint2*)&sAlo[r * LDT + k4] = cal[i];
            }
        } else {
            #pragma unroll
            for (int i = 0; i < 2; ++i) {
                int c = tid + 256 * i;
                int r = c >> 3, k8 = (c & 7) * 8;
                *(uint4*)&sAhi[r * LDT + k8] = rahi[i];
                *(uint4*)&sAlo[r * LDT + k8] = ralo[i];
            }
        }
    };

    // ldmatrix base byte-offsets (within each array)
    uint32_t aOff[2];
    #pragma unroll
    for (int mf = 0; mf < 2; ++mf)
        aOff[mf] = (uint32_t)(((wm + mf * 16 + (lane & 15)) * LDT + (lane >> 4) * 8) * 2);
    const uint32_t bOff = (uint32_t)(((wn + (lane >> 4) * 8 + (lane & 7)) * LDT
                                      + ((lane >> 3) & 1) * 8) * 2);
    const uint32_t aHiB = smem_u32(sAhi), aLoB = smem_u32(sAlo);
    const uint32_t bHiB = smem_u32(sBhi), bLoB = smem_u32(sBlo);

    float acc[2][2][4];
    #pragma unroll
    for (int mf = 0; mf < 2; ++mf)
        #pragma unroll
        for (int nf = 0; nf < 2; ++nf)
            #pragma unroll
            for (int j = 0; j < 4; ++j) acc[mf][nf][j] = 0.f;

    loadRegs(0);
    convRegs();

    for (int kc = 0; kc < 4; ++kc) {
        storeSmem();
        __syncthreads();
        if (kc < 3) loadRegs(kc + 1);   // LDG latency hidden behind MMAs

        #pragma unroll
        for (int ks = 0; ks < 4; ++ks) {
            const uint32_t kByte = ks * 32;
            uint32_t ah[2][4], al[2][4], bh[4], bl[4];
            #pragma unroll
            for (int mf = 0; mf < 2; ++mf) {
                ldsm_x4(ah[mf], aHiB + aOff[mf] + kByte);
                ldsm_x4(al[mf], aLoB + aOff[mf] + kByte);
            }
            ldsm_x4(bh, bHiB + bOff + kByte);
            ldsm_x4(bl, bLoB + bOff + kByte);
            #pragma unroll
            for (int mf = 0; mf < 2; ++mf) {
                #pragma unroll
                for (int nf = 0; nf < 2; ++nf) {
                    mma16816(acc[mf][nf], ah[mf], bh[nf * 2], bh[nf * 2 + 1]); // hi*hi
                    mma16816(acc[mf][nf], ah[mf], bl[nf * 2], bl[nf * 2 + 1]); // hi*lo
                    mma16816(acc[mf][nf], al[mf], bh[nf * 2], bh[nf * 2 + 1]); // lo*hi
                }
            }
        }
        if (kc < 3) {
            convRegs();                 // MUFU for next chunk (off tensor pipe)
            __syncthreads();
        }
    }

    // ---- epilogue ---------------------------------------------------------
    const int l4 = lane >> 2;
    const int l2 = (lane & 3) * 2;
    #pragma unroll
    for (int mf = 0; mf < 2; ++mf) {
        #pragma unroll
        for (int nf = 0; nf < 2; ++nf) {
            int gr = m0 + wm + mf * 16 + l4;
            int gc = n0 + wn + nf * 8 + l2;
            float r[4];
            #pragma unroll
            for (int j = 0; j < 4; ++j) {
                float v = acc[mf][nf][j];
                int col = gc + (j & 1);
                if (MODE == 0) {
                    if (region == 0)      r[j] = v * __expf(b0[col]);
                    else if (region == 1) r[j] = v * __expf(b1[col - 256]);
                    else                  r[j] = __logf(v) + b2[col - 512];
                } else {
                    r[j] = __logf(v) + b0[col];
                }
            }
            *(float2*)&C[gr * ldc + gc]       = make_float2(r[0], r[1]);
            *(float2*)&C[(gr + 8) * ldc + gc] = make_float2(r[2], r[3]);
        }
    }
}

// ---------------------------------------------------------------------------
// Attention: one CTA per (b, h). p = exp(q)*exp(k); attn = p/rowsum;
// out = attn @ v (v = log(Sv)+bv already in g_Y); emit exp(out) as bf16 hi/lo.
// ---------------------------------------------------------------------------
__global__ void k_attn()
{
    __shared__ float P[64][65];
    __shared__ float V[64][68];
    __shared__ float inv[64];

    const int h = blockIdx.x;
    const int b = blockIdx.y;
    const int tid = threadIdx.x;

    for (int i = tid; i < 4096; i += 256) {
        int s = i >> 6, d = i & 63;
        const float* yr = &g_Y[(b * 64 + s) * NQKV + h * 64 + d];
        P[s][d] = yr[0] * yr[256];
    }
    for (int i = tid; i < 4096; i += 256) {
        int d = i >> 6, e = i & 63;
        V[d][e] = g_Y[(b * 64 + d) * NQKV + 512 + h * 64 + e];
    }
    __syncthreads();

    if (tid < 64) {
        float s = 0.f;
        #pragma unroll
        for (int j = 0; j < 64; ++j) s += P[tid][j];
        inv[tid] = 1.0f / s;
    }
    __syncthreads();

    const int tx = tid & 15;
    const int ty = tid >> 4;
    float acc[4][4] = {};

    #pragma unroll 4
    for (int d = 0; d < 64; ++d) {
        float p0 = P[4 * ty + 0][d];
        float p1 = P[4 * ty + 1][d];
        float p2 = P[4 * ty + 2][d];
        float p3 = P[4 * ty + 3][d];
        float4 v4 = *(const float4*)&V[d][4 * tx];
        acc[0][0] += p0 * v4.x; acc[0][1] += p0 * v4.y;
        acc[0][2] += p0 * v4.z; acc[0][3] += p0 * v4.w;
        acc[1][0] += p1 * v4.x; acc[1][1] += p1 * v4.y;
        acc[1][2] += p1 * v4.z; acc[1][3] += p1 * v4.w;
        acc[2][0] += p2 * v4.x; acc[2][1] += p2 * v4.y;
        acc[2][2] += p2 * v4.z; acc[2][3] += p2 * v4.w;
        acc[3][0] += p3 * v4.x; acc[3][1] += p3 * v4.y;
        acc[3][2] += p3 * v4.z; acc[3][3] += p3 * v4.w;
    }

    #pragma unroll
    for (int r = 0; r < 4; ++r) {
        float iv = inv[4 * ty + r];
        int grow = b * 64 + 4 * ty + r;
        #pragma unroll
        for (int c = 0; c < 4; ++c) {
            float eo = __expf(acc[r][c] * iv);
            __nv_bfloat16 hb = __float2bfloat16(eo);
            int gi = grow * EDIM + h * 64 + 4 * tx + c;
            g_EOhi[gi] = hb;
            g_EOlo[gi] = __float2bfloat16(eo - __bfloat162float(hb));
        }
    }
}

// ---------------------------------------------------------------------------
extern "C" void kernel_launch(void* const* d_in, const int* in_sizes, int n_in,
                              void* d_out, int out_size)
{
    const float* x  = (const float*)d_in[0];
    const float* Wq = (const float*)d_in[1];
    const float* bq = (const float*)d_in[2];
    const float* Wk = (const float*)d_in[3];
    const float* bk = (const float*)d_in[4];
    const float* Wv = (const float*)d_in[5];
    const float* bv = (const float*)d_in[6];
    const float* Wo = (const float*)d_in[7];
    const float* bo = (const float*)d_in[8];
    float* out = (float*)d_out;

    float* Y = nullptr; cudaGetSymbolAddress((void**)&Y, g_Y);
    __nv_bfloat16 *EOhi, *EOlo;
    cudaGetSymbolAddress((void**)&EOhi, g_EOhi);
    cudaGetSymbolAddress((void**)&EOlo, g_EOlo);

    // 1. fused QKV GEMM (exp folded into loaders), 384 CTAs
    {
        dim3 grid(NQKV / 64, NROWS / 64);  // (12, 32)
        k_tg<0><<<grid, 256>>>(x, nullptr, Wq, Wk, Wv, Y, NQKV, bq, bk, bv);
    }

    // 2. attention per (b, h)
    {
        dim3 grid(NH, 32);
        k_attn<<<grid, 256>>>();
    }

    // 3. output projection, 128 CTAs: out = log(EO @ exp(Wo)) + bo
    {
        dim3 grid(EDIM / 64, NROWS / 64);  // (4, 32)
        k_tg<1><<<grid, 256>>>(EOhi, EOlo, Wo, Wo, Wo, out, EDIM, bo, bo, bo);
    }
}

// round 7
// speedup vs baseline: 1.2194x; 1.2194x over previous
#include <cuda_runtime.h>
#include <cuda_bf16.h>
#include <cstdint>
#include <math.h>

// Problem constants: B=32, S=64, E=256, H=4, D=64
#define NROWS 2048
#define EDIM  256
#define NQKV  768
#define NH    4

// ---------------- scratch (__device__ globals, no allocs) -------------------
__device__ __nv_bfloat16 g_Ahi[NROWS * EDIM], g_Alo[NROWS * EDIM];   // exp(x) split
__device__ __nv_bfloat16 g_Bhi[NQKV * EDIM],  g_Blo[NQKV * EDIM];    // exp(Wqkv) [n][k]
__device__ __nv_bfloat16 g_Chi[EDIM * EDIM],  g_Clo[EDIM * EDIM];    // exp(Wo)   [n][k]
__device__ __nv_bfloat16 g_EOhi[NROWS * EDIM], g_EOlo[NROWS * EDIM]; // exp(attn out)
__device__ float g_Y[NROWS * NQKV];  // q,k: sum*exp(bias); v: log(sum)+bv

// ---------------- helpers (base ISA only — sm_103 non-variant) --------------
__device__ __forceinline__ uint32_t smem_u32(const void* p) {
    uint32_t a;
    asm("{ .reg .u64 t; cvta.to.shared.u64 t, %1; cvt.u32.u64 %0, t; }"
        : "=r"(a) : "l"(p));
    return a;
}
__device__ __forceinline__ void ldsm_x4(uint32_t* r, uint32_t addr) {
    asm volatile("ldmatrix.sync.aligned.m8n8.x4.shared.b16 {%0,%1,%2,%3}, [%4];"
                 : "=r"(r[0]), "=r"(r[1]), "=r"(r[2]), "=r"(r[3]) : "r"(addr));
}
__device__ __forceinline__ void mma16816(float* d, const uint32_t* a,
                                         uint32_t b0, uint32_t b1) {
    asm volatile(
        "mma.sync.aligned.m16n8k16.row.col.f32.bf16.bf16.f32 "
        "{%0,%1,%2,%3}, {%4,%5,%6,%7}, {%8,%9}, {%0,%1,%2,%3};"
        : "+f"(d[0]), "+f"(d[1]), "+f"(d[2]), "+f"(d[3])
        : "r"(a[0]), "r"(a[1]), "r"(a[2]), "r"(a[3]), "r"(b0), "r"(b1));
}
__device__ __forceinline__ void cp16(uint32_t s, const void* g) {
    asm volatile("cp.async.cg.shared.global [%0], [%1], 16;" :: "r"(s), "l"(g));
}
#define CP_COMMIT() asm volatile("cp.async.commit_group;" ::: "memory")
#define CP_WAIT1()  asm volatile("cp.async.wait_group 1;" ::: "memory")
#define CP_WAIT0()  asm volatile("cp.async.wait_group 0;" ::: "memory")

// ---------------------------------------------------------------------------
// Prep: exp() everything once, split into bf16 hi/lo pairs. float4-vectorized.
// ---------------------------------------------------------------------------
__global__ void k_prep(const float* __restrict__ x,
                       const float* __restrict__ Wq, const float* __restrict__ Wk,
                       const float* __restrict__ Wv, const float* __restrict__ Wo)
{
    int q = blockIdx.x * blockDim.x + threadIdx.x;   // quad index
    const float* src; __nv_bfloat16 *hi, *lo; int idx;
    if (q < (NROWS * EDIM) / 4) {
        idx = q * 4; src = &x[idx]; hi = g_Ahi; lo = g_Alo;
    } else if (q < (NROWS * EDIM + NQKV * EDIM) / 4) {
        idx = q * 4 - NROWS * EDIM;
        int n = idx / EDIM, k = idx - n * EDIM;
        const float* W = (n < 256) ? Wq : ((n < 512) ? Wk : Wv);
        src = &W[(n & 255) * EDIM + k]; hi = g_Bhi; lo = g_Blo;
    } else {
        idx = q * 4 - NROWS * EDIM - NQKV * EDIM;
        src = &Wo[idx]; hi = g_Chi; lo = g_Clo;
    }
    float4 v4 = *(const float4*)src;
    __nv_bfloat16 h[4], l[4];
    float vv[4] = {__expf(v4.x), __expf(v4.y), __expf(v4.z), __expf(v4.w)};
    #pragma unroll
    for (int j = 0; j < 4; ++j) {
        h[j] = __float2bfloat16(vv[j]);
        l[j] = __float2bfloat16(vv[j] - __bfloat162float(h[j]));
    }
    *(uint2*)&hi[idx] = *(uint2*)h;
    *(uint2*)&lo[idx] = *(uint2*)l;
}

// ---------------------------------------------------------------------------
// bf16x3 GEMM via mma.sync, cp.async double-buffered, 256 threads.
//   C[m,n] = sum_k A[m,k]*B[n,k], fp32 accum. CTA 64x64, warp tile 32x16.
//   mode 0 epilogue: n<256 -> acc*exp(bq), n<512 -> acc*exp(bk), else log+bv
//   mode 1 epilogue: log(acc)+bo
// ---------------------------------------------------------------------------
#define LDT 72                         // padded row stride (bf16), 144 B
#define ARR_BYTES (64 * LDT * 2)       // 9216 per array
#define STG_BYTES (4 * ARR_BYTES)      // 36864 per stage: Ahi,Alo,Bhi,Blo
#define SM_TOT    (2 * STG_BYTES)      // 73728

__global__ void __launch_bounds__(256) k_tgemm(
    const __nv_bfloat16* __restrict__ Ahi, const __nv_bfloat16* __restrict__ Alo,
    const __nv_bfloat16* __restrict__ Bhi, const __nv_bfloat16* __restrict__ Blo,
    float* __restrict__ C, int ldc,
    const float* __restrict__ b0, const float* __restrict__ b1,
    const float* __restrict__ b2, int mode)
{
    extern __shared__ char smem[];
    const uint32_t sbase = smem_u32(smem);

    const int tid  = threadIdx.x;
    const int lane = tid & 31;
    const int warp = tid >> 5;
    const int wm   = (warp & 1) * 32;    // warp row offset
    const int wn   = (warp >> 1) * 16;   // warp col offset
    const int m0 = blockIdx.y * 64;
    const int n0 = blockIdx.x * 64;

    // ldmatrix base byte-offsets within an array
    uint32_t aOff[2];
    #pragma unroll
    for (int mf = 0; mf < 2; ++mf)
        aOff[mf] = (uint32_t)(((wm + mf * 16 + (lane & 15)) * LDT + (lane >> 4) * 8) * 2);
    const uint32_t bOff = (uint32_t)(((wn + (lane >> 4) * 8 + (lane & 7)) * LDT
                                      + ((lane >> 3) & 1) * 8) * 2);

    float acc[2][2][4];
    #pragma unroll
    for (int mf = 0; mf < 2; ++mf)
        #pragma unroll
        for (int nf = 0; nf < 2; ++nf)
            #pragma unroll
            for (int j = 0; j < 4; ++j) acc[mf][nf][j] = 0.f;

    // per-thread fill: 512 16B-chunks per array, 2 per thread
    auto prefetch = [&](int kc, int stg) {
        const int kb = kc * 64;
        const uint32_t s0 = sbase + stg * STG_BYTES;
        #pragma unroll
        for (int i = 0; i < 2; ++i) {
            int c = tid + 256 * i;
            int r = c >> 3, k8 = (c & 7) * 8;
            uint32_t so = (r * LDT + k8) * 2;
            cp16(s0 + 0 * ARR_BYTES + so, &Ahi[(m0 + r) * EDIM + kb + k8]);
            cp16(s0 + 1 * ARR_BYTES + so, &Alo[(m0 + r) * EDIM + kb + k8]);
            cp16(s0 + 2 * ARR_BYTES + so, &Bhi[(n0 + r) * EDIM + kb + k8]);
            cp16(s0 + 3 * ARR_BYTES + so, &Blo[(n0 + r) * EDIM + kb + k8]);
        }
        CP_COMMIT();
    };

    prefetch(0, 0);

    for (int kc = 0; kc < 4; ++kc) {
        if (kc < 3) prefetch(kc + 1, (kc + 1) & 1);
        if (kc < 3) CP_WAIT1(); else CP_WAIT0();
        __syncthreads();

        const uint32_t s0 = sbase + (kc & 1) * STG_BYTES;
        #pragma unroll
        for (int ks = 0; ks < 4; ++ks) {
            const uint32_t kByte = ks * 32;  // 16 bf16
            uint32_t ah[2][4], al[2][4], bh[4], bl[4];
            #pragma unroll
            for (int mf = 0; mf < 2; ++mf) {
                ldsm_x4(ah[mf], s0 + 0 * ARR_BYTES + aOff[mf] + kByte);
                ldsm_x4(al[mf], s0 + 1 * ARR_BYTES + aOff[mf] + kByte);
            }
            ldsm_x4(bh, s0 + 2 * ARR_BYTES + bOff + kByte);
            ldsm_x4(bl, s0 + 3 * ARR_BYTES + bOff + kByte);
            #pragma unroll
            for (int mf = 0; mf < 2; ++mf) {
                #pragma unroll
                for (int nf = 0; nf < 2; ++nf) {
                    mma16816(acc[mf][nf], ah[mf], bh[nf * 2], bh[nf * 2 + 1]); // hi*hi
                    mma16816(acc[mf][nf], ah[mf], bl[nf * 2], bl[nf * 2 + 1]); // hi*lo
                    mma16816(acc[mf][nf], al[mf], bh[nf * 2], bh[nf * 2 + 1]); // lo*hi
                }
            }
        }
        __syncthreads();
    }

    // ---- epilogue ---------------------------------------------------------
    const int l4 = lane >> 2;
    const int l2 = (lane & 3) * 2;
    const int region = n0 >> 8;  // mode 0: 0=q, 1=k, 2=v
    #pragma unroll
    for (int mf = 0; mf < 2; ++mf) {
        #pragma unroll
        for (int nf = 0; nf < 2; ++nf) {
            int gr = m0 + wm + mf * 16 + l4;
            int gc = n0 + wn + nf * 8 + l2;
            float r[4];
            #pragma unroll
            for (int j = 0; j < 4; ++j) {
                float v = acc[mf][nf][j];
                int col = gc + (j & 1);
                if (mode == 0) {
                    if (region == 0)      r[j] = v * __expf(b0[col]);
                    else if (region == 1) r[j] = v * __expf(b1[col - 256]);
                    else                  r[j] = __logf(v) + b2[col - 512];
                } else {
                    r[j] = __logf(v) + b0[col];
                }
            }
            *(float2*)&C[gr * ldc + gc]       = make_float2(r[0], r[1]);
            *(float2*)&C[(gr + 8) * ldc + gc] = make_float2(r[2], r[3]);
        }
    }
}

// ---------------------------------------------------------------------------
// Attention: one CTA per (b, h). p = exp(q)*exp(k); attn = p/rowsum;
// out = attn @ v (v = log(Sv)+bv already in g_Y); emit exp(out) as bf16 hi/lo.
// ---------------------------------------------------------------------------
__global__ void k_attn()
{
    __shared__ float P[64][65];
    __shared__ float V[64][68];
    __shared__ float inv[64];

    const int h = blockIdx.x;
    const int b = blockIdx.y;
    const int tid = threadIdx.x;

    for (int i = tid; i < 4096; i += 256) {
        int s = i >> 6, d = i & 63;
        const float* yr = &g_Y[(b * 64 + s) * NQKV + h * 64 + d];
        P[s][d] = yr[0] * yr[256];
    }
    for (int i = tid; i < 4096; i += 256) {
        int d = i >> 6, e = i & 63;
        V[d][e] = g_Y[(b * 64 + d) * NQKV + 512 + h * 64 + e];
    }
    __syncthreads();

    if (tid < 64) {
        float s = 0.f;
        #pragma unroll
        for (int j = 0; j < 64; ++j) s += P[tid][j];
        inv[tid] = 1.0f / s;
    }
    __syncthreads();

    const int tx = tid & 15;
    const int ty = tid >> 4;
    float acc[4][4] = {};

    #pragma unroll 4
    for (int d = 0; d < 64; ++d) {
        float p0 = P[4 * ty + 0][d];
        float p1 = P[4 * ty + 1][d];
        float p2 = P[4 * ty + 2][d];
        float p3 = P[4 * ty + 3][d];
        float4 v4 = *(const float4*)&V[d][4 * tx];
        acc[0][0] += p0 * v4.x; acc[0][1] += p0 * v4.y;
        acc[0][2] += p0 * v4.z; acc[0][3] += p0 * v4.w;
        acc[1][0] += p1 * v4.x; acc[1][1] += p1 * v4.y;
        acc[1][2] += p1 * v4.z; acc[1][3] += p1 * v4.w;
        acc[2][0] += p2 * v4.x; acc[2][1] += p2 * v4.y;
        acc[2][2] += p2 * v4.z; acc[2][3] += p2 * v4.w;
        acc[3][0] += p3 * v4.x; acc[3][1] += p3 * v4.y;
        acc[3][2] += p3 * v4.z; acc[3][3] += p3 * v4.w;
    }

    #pragma unroll
    for (int r = 0; r < 4; ++r) {
        float iv = inv[4 * ty + r];
        int grow = b * 64 + 4 * ty + r;
        #pragma unroll
        for (int c = 0; c < 4; ++c) {
            float eo = __expf(acc[r][c] * iv);
            __nv_bfloat16 hb = __float2bfloat16(eo);
            int gi = grow * EDIM + h * 64 + 4 * tx + c;
            g_EOhi[gi] = hb;
            g_EOlo[gi] = __float2bfloat16(eo - __bfloat162float(hb));
        }
    }
}

// ---------------------------------------------------------------------------
extern "C" void kernel_launch(void* const* d_in, const int* in_sizes, int n_in,
                              void* d_out, int out_size)
{
    const float* x  = (const float*)d_in[0];
    const float* Wq = (const float*)d_in[1];
    const float* bq = (const float*)d_in[2];
    const float* Wk = (const float*)d_in[3];
    const float* bk = (const float*)d_in[4];
    const float* Wv = (const float*)d_in[5];
    const float* bv = (const float*)d_in[6];
    const float* Wo = (const float*)d_in[7];
    const float* bo = (const float*)d_in[8];
    float* out = (float*)d_out;

    static bool attr_set = false;
    if (!attr_set) {
        cudaFuncSetAttribute(k_tgemm, cudaFuncAttributeMaxDynamicSharedMemorySize, SM_TOT);
        attr_set = true;
    }

    float* Y = nullptr; cudaGetSymbolAddress((void**)&Y, g_Y);
    __nv_bfloat16 *Ahi, *Alo, *Bhi, *Blo, *Chi, *Clo, *EOhi, *EOlo;
    cudaGetSymbolAddress((void**)&Ahi, g_Ahi);
    cudaGetSymbolAddress((void**)&Alo, g_Alo);
    cudaGetSymbolAddress((void**)&Bhi, g_Bhi);
    cudaGetSymbolAddress((void**)&Blo, g_Blo);
    cudaGetSymbolAddress((void**)&Chi, g_Chi);
    cudaGetSymbolAddress((void**)&Clo, g_Clo);
    cudaGetSymbolAddress((void**)&EOhi, g_EOhi);
    cudaGetSymbolAddress((void**)&EOlo, g_EOlo);

    // 1. exp + bf16 hi/lo split of all operands, once (786432 elems / 4)
    k_prep<<<768, 256>>>(x, Wq, Wk, Wv, Wo);

    // 2. fused QKV GEMM on tensor pipe (384 CTAs, 8 warps each)
    {
        dim3 grid(NQKV / 64, NROWS / 64);  // (12, 32)
        k_tgemm<<<grid, 256, SM_TOT>>>(Ahi, Alo, Bhi, Blo, Y, NQKV, bq, bk, bv, 0);
    }

    // 3. attention per (b, h)
    {
        dim3 grid(NH, 32);
        k_attn<<<grid, 256>>>();
    }

    // 4. output projection (128 CTAs): out = log(EO @ exp(Wo)) + bo
    {
        dim3 grid(EDIM / 64, NROWS / 64);  // (4, 32)
        k_tgemm<<<grid, 256, SM_TOT>>>(EOhi, EOlo, Chi, Clo, out, EDIM, bo, nullptr, nullptr, 1);
    }
}